// round 5
// baseline (speedup 1.0000x reference)
#include <cuda_runtime.h>
#include <cuda_bf16.h>

#define L_IN  1024
#define L_ENC 1024
#define BATCH 16
#define D     512
#define ROWS  (L_IN * BATCH)   // 16384

// Scratch (device globals)
__device__ float g_dvals[ROWS * D];     // [l*B+b][e]
__device__ float g_context[ROWS * D];   // [l*B+b][e]

// ---------------------------------------------------------------------------
// K1: d_vals[lb][e] = fl( fl(asc_dot(in_row, W1[e]) + b1[e])
//                       + fl(asc_dot(tgt_row, W2[e]) + b2[e]) )
// ---------------------------------------------------------------------------
__global__ __launch_bounds__(512) void k_dvals(
    const float* __restrict__ in_seq, const float* __restrict__ tgt,
    const float* __restrict__ W1, const float* __restrict__ W2,
    const float* __restrict__ b1, const float* __restrict__ b2)
{
    __shared__ float in_s[4][D];
    __shared__ float tg_s[4][D];
    const int e   = threadIdx.x;
    const int lb0 = blockIdx.x * 4;

    for (int idx = e; idx < 4 * D; idx += 512) {
        const int j = idx >> 9, c = idx & (D - 1);
        in_s[j][c] = in_seq[(size_t)(lb0 + j) * D + c];
        tg_s[j][c] = tgt[(size_t)(lb0 + j) * D + c];
    }
    __syncthreads();

    const float* w1r = W1 + (size_t)e * D;
    const float* w2r = W2 + (size_t)e * D;
    float a1[4] = {}, a2[4] = {};
    for (int i = 0; i < D; ++i) {
        const float w1 = w1r[i];
        const float w2 = w2r[i];
#pragma unroll
        for (int j = 0; j < 4; ++j) {
            a1[j] = fmaf(in_s[j][i], w1, a1[j]);
            a2[j] = fmaf(tg_s[j][i], w2, a2[j]);
        }
    }
    const float bb1 = b1[e], bb2 = b2[e];
#pragma unroll
    for (int j = 0; j < 4; ++j)
        g_dvals[(size_t)(lb0 + j) * D + e] = (a1[j] + bb1) + (a2[j] + bb2);
}

// ---------------------------------------------------------------------------
// K2 (fused): per block = (8 l-rows, one b)
//   B: scores s[j][m]  = asc-e FMA dot(d_vals, enc_m)      (cublas-like)
//   C: rowsum          = XLA-GPU row-reduce emulation:
//        64 thr/row, 16-term ascending strided (stride 64) partials,
//        per-warp shfl.down tree (16,8,4,2,1), inter-warp P0+P1
//   D: attn            = __fdiv_rn(s, R)
//   E: context[j][e]   = asc-m FMA sum attn*enc
// ---------------------------------------------------------------------------
__global__ __launch_bounds__(1024) void k_fused(const float* __restrict__ enc)
{
    extern __shared__ float sm[];
    float* d_s = sm;                  // [8][512]
    float* s_s = sm + 8 * D;          // [8][1024]
    float* R_s = sm + 8 * D + 8 * L_ENC;   // [8]

    __shared__ float warp_part[16];

    const int tid = threadIdx.x;      // 0..1023
    const int l0  = blockIdx.x * 8;
    const int b   = blockIdx.y;

    // Phase A: stage d_vals rows
    for (int idx = tid; idx < 8 * D; idx += 1024) {
        const int j = idx >> 9, c = idx & (D - 1);
        d_s[idx] = g_dvals[((size_t)(l0 + j) * BATCH + b) * D + c];
    }
    __syncthreads();

    // Phase B: scores — thread = m, ascending-e FMA, 8 rows at once
    {
        const int m = tid;
        const float* er = enc + ((size_t)m * BATCH + b) * D;
        float acc[8] = {};
        for (int e2 = 0; e2 < D; ++e2) {
            const float ev = er[e2];
#pragma unroll
            for (int j = 0; j < 8; ++j)
                acc[j] = fmaf(d_s[j * D + e2], ev, acc[j]);
        }
#pragma unroll
        for (int j = 0; j < 8; ++j)
            s_s[j * L_ENC + m] = acc[j];
    }
    __syncthreads();

    // Phase C: rowsum — XLA row-reduction emulation
    if (tid < 512) {
        const int j = tid >> 6;              // row 0..7
        const int t = tid & 63;              // thread-in-row 0..63
        const float* sr = s_s + j * L_ENC;
        float a = 0.f;
#pragma unroll
        for (int i = 0; i < 16; ++i)         // ascending strided chain
            a += sr[t + (i << 6)];
#pragma unroll
        for (int o = 16; o; o >>= 1)         // warp shfl.down tree
            a += __shfl_down_sync(0xFFFFFFFFu, a, o);
        if ((t & 31) == 0)
            warp_part[tid >> 5] = a;         // warp id = 2j + (t>>5)
    }
    __syncthreads();
    if (tid < 8)
        R_s[tid] = warp_part[2 * tid] + warp_part[2 * tid + 1];
    __syncthreads();

    // Phase D: attn = scores / rowsum (IEEE division)
    for (int idx = tid; idx < 8 * L_ENC; idx += 1024)
        s_s[idx] = __fdiv_rn(s_s[idx], R_s[idx >> 10]);
    __syncthreads();

    // Phase E: context — thread = (e, j0), 4 j's per thread, ascending-m FMA
    {
        const int e2 = tid & (D - 1);
        const int j0 = tid >> 9;             // 0 or 1
        float acc[4] = {};
        for (int m = 0; m < L_ENC; ++m) {
            const float ev = enc[((size_t)m * BATCH + b) * D + e2];
#pragma unroll
            for (int t = 0; t < 4; ++t)
                acc[t] = fmaf(s_s[(j0 + 2 * t) * L_ENC + m], ev, acc[t]);
        }
#pragma unroll
        for (int t = 0; t < 4; ++t) {
            const int j = j0 + 2 * t;
            g_context[((size_t)(l0 + j) * BATCH + b) * D + e2] = acc[t];
        }
    }
}

// ---------------------------------------------------------------------------
// K3: out[lb][i] = fl( asc-e FMA dot(context[lb,:], W3[i,:]) + b3[i] )
// ---------------------------------------------------------------------------
__global__ __launch_bounds__(512) void k_out(
    const float* __restrict__ W3, const float* __restrict__ b3,
    float* __restrict__ out)
{
    __shared__ float c_s[4][D];
    const int i   = threadIdx.x;
    const int lb0 = blockIdx.x * 4;

    for (int idx = i; idx < 4 * D; idx += 512) {
        const int j = idx >> 9, c = idx & (D - 1);
        c_s[j][c] = g_context[(size_t)(lb0 + j) * D + c];
    }
    __syncthreads();

    const float* wr = W3 + (size_t)i * D;
    float acc[4] = {};
    for (int e = 0; e < D; ++e) {
        const float w = wr[e];
#pragma unroll
        for (int j = 0; j < 4; ++j)
            acc[j] = fmaf(c_s[j][e], w, acc[j]);
    }
    const float bv = b3[i];
#pragma unroll
    for (int j = 0; j < 4; ++j)
        out[(size_t)(lb0 + j) * D + i] = acc[j] + bv;
}

// ---------------------------------------------------------------------------
extern "C" void kernel_launch(void* const* d_in, const int* in_sizes, int n_in,
                              void* d_out, int out_size)
{
    const float* in_seq   = (const float*)d_in[0];
    const float* enc_seq  = (const float*)d_in[1];
    const float* prev_tgt = (const float*)d_in[2];
    const float* W_in2enc = (const float*)d_in[3];
    const float* b_in2enc = (const float*)d_in[4];
    const float* W_lab2enc= (const float*)d_in[5];
    const float* b_lab2enc= (const float*)d_in[6];
    const float* W_enc2in = (const float*)d_in[7];
    const float* b_enc2in = (const float*)d_in[8];
    float* out = (float*)d_out;

    static bool attr_set = false;
    if (!attr_set) {
        cudaFuncSetAttribute(k_fused, cudaFuncAttributeMaxDynamicSharedMemorySize,
                             (8 * D + 8 * L_ENC + 8) * sizeof(float));
        attr_set = true;
    }
    const int smem = (8 * D + 8 * L_ENC + 8) * sizeof(float);

    k_dvals<<<ROWS / 4, 512>>>(in_seq, prev_tgt, W_in2enc, W_lab2enc,
                               b_in2enc, b_lab2enc);
    k_fused<<<dim3(L_IN / 8, BATCH), 1024, smem>>>(enc_seq);
    k_out<<<ROWS / 4, 512>>>(W_enc2in, b_enc2in, out);
}

// round 9
// speedup vs baseline: 8.7221x; 8.7221x over previous
#include <cuda_runtime.h>
#include <cuda_bf16.h>

#define L_IN  1024
#define L_ENC 1024
#define BATCH 16
#define D     512
#define ROWS  (L_IN * BATCH)   // 16384

#define TM 64
#define TN 64
#define BK 16

// Scratch (device globals)
__device__ float g_dvals[ROWS * D];               // [b][l][e]
__device__ float g_scores[(size_t)BATCH * L_IN * L_ENC]; // [b][l][m]
__device__ float g_ctx[ROWS * D];                 // [b][l][e]
__device__ float g_R[BATCH * L_IN];               // [b*1024+l]

// ---------------------------------------------------------------------------
// K1: d_vals = fl(fl(asc_dot(in,W1)+b1) + fl(asc_dot(tgt,W2)+b2))
// Register-tiled: 64x64 tile, 4x4 microtile, BK=16, dual accumulators.
// Per-output order: single accumulator, ascending k (bit-identical to R5).
// ---------------------------------------------------------------------------
__global__ __launch_bounds__(256) void k_dvals(
    const float* __restrict__ in_seq, const float* __restrict__ tgt,
    const float* __restrict__ W1, const float* __restrict__ W2,
    const float* __restrict__ b1, const float* __restrict__ b2)
{
    __shared__ float As1[BK][TM], As2[BK][TM], Bs1[BK][TN], Bs2[BK][TN];
    const int tid = threadIdx.x;
    const int tx = tid & 15, ty = tid >> 4;
    const int row0 = blockIdx.y * TM;       // lb rows (natural order)
    const int col0 = blockIdx.x * TN;       // e cols
    const int lr = tid >> 2;                // 0..63
    const int lk = (tid & 3) * 4;           // k offset

    float acc1[4][4] = {}, acc2[4][4] = {};

    for (int k0 = 0; k0 < D; k0 += BK) {
        float4 a1 = *reinterpret_cast<const float4*>(&in_seq[(size_t)(row0 + lr) * D + k0 + lk]);
        float4 a2 = *reinterpret_cast<const float4*>(&tgt   [(size_t)(row0 + lr) * D + k0 + lk]);
        float4 w1 = *reinterpret_cast<const float4*>(&W1    [(size_t)(col0 + lr) * D + k0 + lk]);
        float4 w2 = *reinterpret_cast<const float4*>(&W2    [(size_t)(col0 + lr) * D + k0 + lk]);
        __syncthreads();
        As1[lk + 0][lr] = a1.x; As1[lk + 1][lr] = a1.y; As1[lk + 2][lr] = a1.z; As1[lk + 3][lr] = a1.w;
        As2[lk + 0][lr] = a2.x; As2[lk + 1][lr] = a2.y; As2[lk + 2][lr] = a2.z; As2[lk + 3][lr] = a2.w;
        Bs1[lk + 0][lr] = w1.x; Bs1[lk + 1][lr] = w1.y; Bs1[lk + 2][lr] = w1.z; Bs1[lk + 3][lr] = w1.w;
        Bs2[lk + 0][lr] = w2.x; Bs2[lk + 1][lr] = w2.y; Bs2[lk + 2][lr] = w2.z; Bs2[lk + 3][lr] = w2.w;
        __syncthreads();
#pragma unroll
        for (int kk = 0; kk < BK; ++kk) {
            float4 av1 = *reinterpret_cast<const float4*>(&As1[kk][4 * ty]);
            float4 av2 = *reinterpret_cast<const float4*>(&As2[kk][4 * ty]);
            float4 bv1 = *reinterpret_cast<const float4*>(&Bs1[kk][4 * tx]);
            float4 bv2 = *reinterpret_cast<const float4*>(&Bs2[kk][4 * tx]);
            const float a1v[4] = {av1.x, av1.y, av1.z, av1.w};
            const float a2v[4] = {av2.x, av2.y, av2.z, av2.w};
            const float b1v[4] = {bv1.x, bv1.y, bv1.z, bv1.w};
            const float b2v[4] = {bv2.x, bv2.y, bv2.z, bv2.w};
#pragma unroll
            for (int i = 0; i < 4; ++i)
#pragma unroll
                for (int j = 0; j < 4; ++j) {
                    acc1[i][j] = fmaf(a1v[i], b1v[j], acc1[i][j]);
                    acc2[i][j] = fmaf(a2v[i], b2v[j], acc2[i][j]);
                }
        }
    }
    const int cbase = col0 + 4 * tx;
    const float4 bb1 = *reinterpret_cast<const float4*>(&b1[cbase]);
    const float4 bb2 = *reinterpret_cast<const float4*>(&b2[cbase]);
    const float b1v[4] = {bb1.x, bb1.y, bb1.z, bb1.w};
    const float b2v[4] = {bb2.x, bb2.y, bb2.z, bb2.w};
#pragma unroll
    for (int i = 0; i < 4; ++i) {
        const int r = row0 + 4 * ty + i;          // lb = l*16+b
        const int b = r & 15, l = r >> 4;
        float4 v;
        v.x = (acc1[i][0] + b1v[0]) + (acc2[i][0] + b2v[0]);
        v.y = (acc1[i][1] + b1v[1]) + (acc2[i][1] + b2v[1]);
        v.z = (acc1[i][2] + b1v[2]) + (acc2[i][2] + b2v[2]);
        v.w = (acc1[i][3] + b1v[3]) + (acc2[i][3] + b2v[3]);
        *reinterpret_cast<float4*>(&g_dvals[((size_t)b * L_IN + l) * D + cbase]) = v;
    }
}

// ---------------------------------------------------------------------------
// K2: scores[b][l][m] = asc-e FMA dot(d_vals[b][l][:], enc[m][b][:])
// ---------------------------------------------------------------------------
__global__ __launch_bounds__(256) void k_scores(const float* __restrict__ enc)
{
    __shared__ float As[BK][TM], Bs[BK][TN];
    const int tid = threadIdx.x;
    const int tx = tid & 15, ty = tid >> 4;
    const int l0 = blockIdx.y * TM;
    const int m0 = blockIdx.x * TN;
    const int b  = blockIdx.z;
    const int lr = tid >> 2;
    const int lk = (tid & 3) * 4;

    float acc[4][4] = {};

    for (int k0 = 0; k0 < D; k0 += BK) {
        float4 a = *reinterpret_cast<const float4*>(
            &g_dvals[((size_t)b * L_IN + l0 + lr) * D + k0 + lk]);
        float4 e = *reinterpret_cast<const float4*>(
            &enc[((size_t)(m0 + lr) * BATCH + b) * D + k0 + lk]);
        __syncthreads();
        As[lk + 0][lr] = a.x; As[lk + 1][lr] = a.y; As[lk + 2][lr] = a.z; As[lk + 3][lr] = a.w;
        Bs[lk + 0][lr] = e.x; Bs[lk + 1][lr] = e.y; Bs[lk + 2][lr] = e.z; Bs[lk + 3][lr] = e.w;
        __syncthreads();
#pragma unroll
        for (int kk = 0; kk < BK; ++kk) {
            float4 av = *reinterpret_cast<const float4*>(&As[kk][4 * ty]);
            float4 bv = *reinterpret_cast<const float4*>(&Bs[kk][4 * tx]);
            const float av4[4] = {av.x, av.y, av.z, av.w};
            const float bv4[4] = {bv.x, bv.y, bv.z, bv.w};
#pragma unroll
            for (int i = 0; i < 4; ++i)
#pragma unroll
                for (int j = 0; j < 4; ++j)
                    acc[i][j] = fmaf(av4[i], bv4[j], acc[i][j]);
        }
    }
#pragma unroll
    for (int i = 0; i < 4; ++i) {
        const int l = l0 + 4 * ty + i;
        float4 v = {acc[i][0], acc[i][1], acc[i][2], acc[i][3]};
        *reinterpret_cast<float4*>(
            &g_scores[((size_t)b * L_IN + l) * L_ENC + m0 + 4 * tx]) = v;
    }
}

// ---------------------------------------------------------------------------
// K3: rowsum — exact XLA row-reduce emulation (bit-identical to R5 phase C):
// 64 thr/row, 16-term ascending strided partials, shfl.down tree, pair add.
// ---------------------------------------------------------------------------
__global__ __launch_bounds__(512) void k_rowsum()
{
    __shared__ float warp_part[16];
    const int tid = threadIdx.x;
    const int row0 = blockIdx.x * 8;
    const int j = tid >> 6;               // row-in-block 0..7
    const int t = tid & 63;
    const float* sr = g_scores + (size_t)(row0 + j) * L_ENC;
    float a = 0.f;
#pragma unroll
    for (int i = 0; i < 16; ++i)
        a += sr[t + (i << 6)];
#pragma unroll
    for (int o = 16; o; o >>= 1)
        a += __shfl_down_sync(0xFFFFFFFFu, a, o);
    if ((t & 31) == 0)
        warp_part[tid >> 5] = a;
    __syncthreads();
    if (tid < 8)
        g_R[row0 + tid] = warp_part[2 * tid] + warp_part[2 * tid + 1];
}

// ---------------------------------------------------------------------------
// K4: context[b][l][e] = asc-m FMA sum of __fdiv_rn(s[l][m],R[l]) * enc[m][b][e]
// Register-tiled over K=m. Division applied at A-tile load (== reference attn).
// ---------------------------------------------------------------------------
__global__ __launch_bounds__(256) void k_context(const float* __restrict__ enc)
{
    __shared__ float As[BK][TM], Bs[BK][TN];
    const int tid = threadIdx.x;
    const int tx = tid & 15, ty = tid >> 4;
    const int l0 = blockIdx.y * TM;
    const int e0 = blockIdx.x * TN;
    const int b  = blockIdx.z;
    const int lr = tid >> 2;
    const int lk = (tid & 3) * 4;
    const int br = tid >> 4;              // 0..15 (B-tile row = m)
    const int bc = (tid & 15) * 4;        // B-tile col (e)

    const float Rv = g_R[(size_t)b * L_IN + l0 + lr];

    float acc[4][4] = {};

    for (int k0 = 0; k0 < L_ENC; k0 += BK) {
        float4 s = *reinterpret_cast<const float4*>(
            &g_scores[((size_t)b * L_IN + l0 + lr) * L_ENC + k0 + lk]);
        s.x = __fdiv_rn(s.x, Rv); s.y = __fdiv_rn(s.y, Rv);
        s.z = __fdiv_rn(s.z, Rv); s.w = __fdiv_rn(s.w, Rv);
        float4 e = *reinterpret_cast<const float4*>(
            &enc[((size_t)(k0 + br) * BATCH + b) * D + e0 + bc]);
        __syncthreads();
        As[lk + 0][lr] = s.x; As[lk + 1][lr] = s.y; As[lk + 2][lr] = s.z; As[lk + 3][lr] = s.w;
        *reinterpret_cast<float4*>(&Bs[br][bc]) = e;
        __syncthreads();
#pragma unroll
        for (int kk = 0; kk < BK; ++kk) {
            float4 av = *reinterpret_cast<const float4*>(&As[kk][4 * ty]);
            float4 bv = *reinterpret_cast<const float4*>(&Bs[kk][4 * tx]);
            const float av4[4] = {av.x, av.y, av.z, av.w};
            const float bv4[4] = {bv.x, bv.y, bv.z, bv.w};
#pragma unroll
            for (int i = 0; i < 4; ++i)
#pragma unroll
                for (int j = 0; j < 4; ++j)
                    acc[i][j] = fmaf(av4[i], bv4[j], acc[i][j]);
        }
    }
#pragma unroll
    for (int i = 0; i < 4; ++i) {
        const int l = l0 + 4 * ty + i;
        float4 v = {acc[i][0], acc[i][1], acc[i][2], acc[i][3]};
        *reinterpret_cast<float4*>(
            &g_ctx[((size_t)b * L_IN + l) * D + e0 + 4 * tx]) = v;
    }
}

// ---------------------------------------------------------------------------
// K5: out[(l*16+b)][i] = fl(asc-e FMA dot(ctx[b][l][:], W3[i][:]) + b3[i])
// ---------------------------------------------------------------------------
__global__ __launch_bounds__(256) void k_out(
    const float* __restrict__ W3, const float* __restrict__ b3,
    float* __restrict__ out)
{
    __shared__ float As[BK][TM], Bs[BK][TN];
    const int tid = threadIdx.x;
    const int tx = tid & 15, ty = tid >> 4;
    const int row0 = blockIdx.y * TM;     // rows in (b*1024+l) order
    const int col0 = blockIdx.x * TN;     // i cols
    const int lr = tid >> 2;
    const int lk = (tid & 3) * 4;

    float acc[4][4] = {};

    for (int k0 = 0; k0 < D; k0 += BK) {
        float4 a = *reinterpret_cast<const float4*>(
            &g_ctx[(size_t)(row0 + lr) * D + k0 + lk]);
        float4 w = *reinterpret_cast<const float4*>(
            &W3[(size_t)(col0 + lr) * D + k0 + lk]);
        __syncthreads();
        As[lk + 0][lr] = a.x; As[lk + 1][lr] = a.y; As[lk + 2][lr] = a.z; As[lk + 3][lr] = a.w;
        Bs[lk + 0][lr] = w.x; Bs[lk + 1][lr] = w.y; Bs[lk + 2][lr] = w.z; Bs[lk + 3][lr] = w.w;
        __syncthreads();
#pragma unroll
        for (int kk = 0; kk < BK; ++kk) {
            float4 av = *reinterpret_cast<const float4*>(&As[kk][4 * ty]);
            float4 bv = *reinterpret_cast<const float4*>(&Bs[kk][4 * tx]);
            const float av4[4] = {av.x, av.y, av.z, av.w};
            const float bv4[4] = {bv.x, bv.y, bv.z, bv.w};
#pragma unroll
            for (int i = 0; i < 4; ++i)
#pragma unroll
                for (int j = 0; j < 4; ++j)
                    acc[i][j] = fmaf(av4[i], bv4[j], acc[i][j]);
        }
    }
    const int cbase = col0 + 4 * tx;
    const float4 bb = *reinterpret_cast<const float4*>(&b3[cbase]);
    const float bv4[4] = {bb.x, bb.y, bb.z, bb.w};
#pragma unroll
    for (int i = 0; i < 4; ++i) {
        const int r = row0 + 4 * ty + i;      // b*1024 + l
        const int b = r >> 10, l = r & (L_IN - 1);
        float4 v;
        v.x = acc[i][0] + bv4[0]; v.y = acc[i][1] + bv4[1];
        v.z = acc[i][2] + bv4[2]; v.w = acc[i][3] + bv4[3];
        *reinterpret_cast<float4*>(&out[((size_t)l * BATCH + b) * D + cbase]) = v;
    }
}

// ---------------------------------------------------------------------------
extern "C" void kernel_launch(void* const* d_in, const int* in_sizes, int n_in,
                              void* d_out, int out_size)
{
    const float* in_seq   = (const float*)d_in[0];
    const float* enc_seq  = (const float*)d_in[1];
    const float* prev_tgt = (const float*)d_in[2];
    const float* W_in2enc = (const float*)d_in[3];
    const float* b_in2enc = (const float*)d_in[4];
    const float* W_lab2enc= (const float*)d_in[5];
    const float* b_lab2enc= (const float*)d_in[6];
    const float* W_enc2in = (const float*)d_in[7];
    const float* b_enc2in = (const float*)d_in[8];
    float* out = (float*)d_out;

    k_dvals  <<<dim3(D / TN, ROWS / TM), 256>>>(in_seq, prev_tgt,
                  W_in2enc, W_lab2enc, b_in2enc, b_lab2enc);
    k_scores <<<dim3(L_ENC / TN, L_IN / TM, BATCH), 256>>>(enc_seq);
    k_rowsum <<<BATCH * L_IN / 8, 512>>>();
    k_context<<<dim3(D / TN, L_IN / TM, BATCH), 256>>>(enc_seq);
    k_out    <<<dim3(D / TN, ROWS / TM), 256>>>(W_enc2in, b_enc2in, out);
}

// round 10
// speedup vs baseline: 10.1997x; 1.1694x over previous
#include <cuda_runtime.h>
#include <cuda_bf16.h>

#define L_IN  1024
#define L_ENC 1024
#define BATCH 16
#define D     512
#define ROWS  (L_IN * BATCH)   // 16384

#define TM 128
#define TN 128
#define BK 8

// Scratch (device globals)
__device__ float g_dvals[ROWS * D];                      // [b][l][e]
__device__ float g_scores[(size_t)BATCH * L_IN * L_ENC]; // [b][l][m]
__device__ float g_ctx[ROWS * D];                        // [b][l][e]
__device__ float g_R[BATCH * L_IN];                      // [b*1024+l]

// ---------------------------------------------------------------------------
// Shared GEMM microkernel body (128x128 tile, BK=8, 256 thr, 8x8/thread).
// Every output: single accumulator, ascending-k FMA — frozen order.
// ---------------------------------------------------------------------------
#define GEMM_INNER(As, Bs, acc)                                              \
    _Pragma("unroll")                                                        \
    for (int kk = 0; kk < BK; ++kk) {                                        \
        float a[8], bb[8];                                                   \
        *reinterpret_cast<float4*>(&a[0])  = *reinterpret_cast<const float4*>(&As[kk][4 * ty]);       \
        *reinterpret_cast<float4*>(&a[4])  = *reinterpret_cast<const float4*>(&As[kk][64 + 4 * ty]);  \
        *reinterpret_cast<float4*>(&bb[0]) = *reinterpret_cast<const float4*>(&Bs[kk][4 * tx]);       \
        *reinterpret_cast<float4*>(&bb[4]) = *reinterpret_cast<const float4*>(&Bs[kk][64 + 4 * tx]);  \
        _Pragma("unroll")                                                    \
        for (int i = 0; i < 8; ++i)                                          \
            _Pragma("unroll")                                                \
            for (int j = 0; j < 8; ++j)                                      \
                acc[i][j] = fmaf(a[i], bb[j], acc[i][j]);                    \
    }

// ---------------------------------------------------------------------------
// K1a: g_dvals[b][l][e] = fl(asc_dot(in_row, W1[e]) + b1[e])
// A rows: lb natural (l*16+b). B: W1 rows (K-major).
// ---------------------------------------------------------------------------
__global__ __launch_bounds__(256) void k_proj1(
    const float* __restrict__ A, const float* __restrict__ W,
    const float* __restrict__ bias)
{
    __shared__ float As[BK][TM], Bs[BK][TN];
    const int tid = threadIdx.x;
    const int tx = tid & 15, ty = tid >> 4;
    const int row0 = blockIdx.y * TM;
    const int col0 = blockIdx.x * TN;
    const int lr = tid >> 1;            // 0..127
    const int lk = (tid & 1) * 4;       // 0 or 4

    float acc[8][8] = {};

    for (int k0 = 0; k0 < D; k0 += BK) {
        float4 a = *reinterpret_cast<const float4*>(&A[(size_t)(row0 + lr) * D + k0 + lk]);
        float4 w = *reinterpret_cast<const float4*>(&W[(size_t)(col0 + lr) * D + k0 + lk]);
        __syncthreads();
        As[lk + 0][lr] = a.x; As[lk + 1][lr] = a.y; As[lk + 2][lr] = a.z; As[lk + 3][lr] = a.w;
        Bs[lk + 0][lr] = w.x; Bs[lk + 1][lr] = w.y; Bs[lk + 2][lr] = w.z; Bs[lk + 3][lr] = w.w;
        __syncthreads();
        GEMM_INNER(As, Bs, acc)
    }
#pragma unroll
    for (int half = 0; half < 2; ++half) {
        const int cbase = col0 + 64 * half + 4 * tx;
        const float4 bb = *reinterpret_cast<const float4*>(&bias[cbase]);
        const float bv[4] = {bb.x, bb.y, bb.z, bb.w};
#pragma unroll
        for (int i = 0; i < 8; ++i) {
            const int r = row0 + (i < 4 ? 4 * ty + i : 64 + 4 * ty + (i - 4));
            const int b = r & 15, l = r >> 4;
            float4 v;
            v.x = acc[i][4 * half + 0] + bv[0];
            v.y = acc[i][4 * half + 1] + bv[1];
            v.z = acc[i][4 * half + 2] + bv[2];
            v.w = acc[i][4 * half + 3] + bv[3];
            *reinterpret_cast<float4*>(&g_dvals[((size_t)b * L_IN + l) * D + cbase]) = v;
        }
    }
}

// ---------------------------------------------------------------------------
// K1b: g_dvals += fl(asc_dot(tgt_row, W2[e]) + b2[e])
//   final = fl(stored + fl(dot2+b2)) == fl(fl(dot1+b1)+fl(dot2+b2))  (bitwise)
// ---------------------------------------------------------------------------
__global__ __launch_bounds__(256) void k_proj2(
    const float* __restrict__ A, const float* __restrict__ W,
    const float* __restrict__ bias)
{
    __shared__ float As[BK][TM], Bs[BK][TN];
    const int tid = threadIdx.x;
    const int tx = tid & 15, ty = tid >> 4;
    const int row0 = blockIdx.y * TM;
    const int col0 = blockIdx.x * TN;
    const int lr = tid >> 1;
    const int lk = (tid & 1) * 4;

    float acc[8][8] = {};

    for (int k0 = 0; k0 < D; k0 += BK) {
        float4 a = *reinterpret_cast<const float4*>(&A[(size_t)(row0 + lr) * D + k0 + lk]);
        float4 w = *reinterpret_cast<const float4*>(&W[(size_t)(col0 + lr) * D + k0 + lk]);
        __syncthreads();
        As[lk + 0][lr] = a.x; As[lk + 1][lr] = a.y; As[lk + 2][lr] = a.z; As[lk + 3][lr] = a.w;
        Bs[lk + 0][lr] = w.x; Bs[lk + 1][lr] = w.y; Bs[lk + 2][lr] = w.z; Bs[lk + 3][lr] = w.w;
        __syncthreads();
        GEMM_INNER(As, Bs, acc)
    }
#pragma unroll
    for (int half = 0; half < 2; ++half) {
        const int cbase = col0 + 64 * half + 4 * tx;
        const float4 bb = *reinterpret_cast<const float4*>(&bias[cbase]);
        const float bv[4] = {bb.x, bb.y, bb.z, bb.w};
#pragma unroll
        for (int i = 0; i < 8; ++i) {
            const int r = row0 + (i < 4 ? 4 * ty + i : 64 + 4 * ty + (i - 4));
            const int b = r & 15, l = r >> 4;
            float* dst = &g_dvals[((size_t)b * L_IN + l) * D + cbase];
            float4 prev = *reinterpret_cast<const float4*>(dst);
            float4 v;
            v.x = prev.x + (acc[i][4 * half + 0] + bv[0]);
            v.y = prev.y + (acc[i][4 * half + 1] + bv[1]);
            v.z = prev.z + (acc[i][4 * half + 2] + bv[2]);
            v.w = prev.w + (acc[i][4 * half + 3] + bv[3]);
            *reinterpret_cast<float4*>(dst) = v;
        }
    }
}

// ---------------------------------------------------------------------------
// K2: scores[b][l][m] = asc-e FMA dot(d_vals[b][l][:], enc[m][b][:])
// ---------------------------------------------------------------------------
__global__ __launch_bounds__(256) void k_scores(const float* __restrict__ enc)
{
    __shared__ float As[BK][TM], Bs[BK][TN];
    const int tid = threadIdx.x;
    const int tx = tid & 15, ty = tid >> 4;
    const int l0 = blockIdx.y * TM;
    const int m0 = blockIdx.x * TN;
    const int b  = blockIdx.z;
    const int lr = tid >> 1;
    const int lk = (tid & 1) * 4;

    float acc[8][8] = {};

    for (int k0 = 0; k0 < D; k0 += BK) {
        float4 a = *reinterpret_cast<const float4*>(
            &g_dvals[((size_t)b * L_IN + l0 + lr) * D + k0 + lk]);
        float4 e = *reinterpret_cast<const float4*>(
            &enc[((size_t)(m0 + lr) * BATCH + b) * D + k0 + lk]);
        __syncthreads();
        As[lk + 0][lr] = a.x; As[lk + 1][lr] = a.y; As[lk + 2][lr] = a.z; As[lk + 3][lr] = a.w;
        Bs[lk + 0][lr] = e.x; Bs[lk + 1][lr] = e.y; Bs[lk + 2][lr] = e.z; Bs[lk + 3][lr] = e.w;
        __syncthreads();
        GEMM_INNER(As, Bs, acc)
    }
#pragma unroll
    for (int i = 0; i < 8; ++i) {
        const int l = l0 + (i < 4 ? 4 * ty + i : 64 + 4 * ty + (i - 4));
        float* base = &g_scores[((size_t)b * L_IN + l) * L_ENC + m0];
        float4 v0 = {acc[i][0], acc[i][1], acc[i][2], acc[i][3]};
        float4 v1 = {acc[i][4], acc[i][5], acc[i][6], acc[i][7]};
        *reinterpret_cast<float4*>(base + 4 * tx) = v0;
        *reinterpret_cast<float4*>(base + 64 + 4 * tx) = v1;
    }
}

// ---------------------------------------------------------------------------
// K3: rowsum — exact XLA row-reduce emulation (FROZEN, bit-identical to R5):
// 64 thr/row, 16-term ascending strided partials, shfl.down tree, pair add.
// ---------------------------------------------------------------------------
__global__ __launch_bounds__(512) void k_rowsum()
{
    __shared__ float warp_part[16];
    const int tid = threadIdx.x;
    const int row0 = blockIdx.x * 8;
    const int j = tid >> 6;
    const int t = tid & 63;
    const float* sr = g_scores + (size_t)(row0 + j) * L_ENC;
    float a = 0.f;
#pragma unroll
    for (int i = 0; i < 16; ++i)
        a += sr[t + (i << 6)];
#pragma unroll
    for (int o = 16; o; o >>= 1)
        a += __shfl_down_sync(0xFFFFFFFFu, a, o);
    if ((t & 31) == 0)
        warp_part[tid >> 5] = a;
    __syncthreads();
    if (tid < 8)
        g_R[row0 + tid] = warp_part[2 * tid] + warp_part[2 * tid + 1];
}

// ---------------------------------------------------------------------------
// K4: context[b][l][e] = asc-m FMA sum of __fdiv_rn(s[l][m],R[l]) * enc[m][b][e]
// Division applied at A-tile load (== reference attn elementwise op).
// ---------------------------------------------------------------------------
__global__ __launch_bounds__(256) void k_context(const float* __restrict__ enc)
{
    __shared__ float As[BK][TM], Bs[BK][TN];
    const int tid = threadIdx.x;
    const int tx = tid & 15, ty = tid >> 4;
    const int l0 = blockIdx.y * TM;
    const int e0 = blockIdx.x * TN;
    const int b  = blockIdx.z;
    const int lr = tid >> 1;            // A row (l) 0..127
    const int lk = (tid & 1) * 4;
    const int br = tid >> 5;            // B row (m) 0..7
    const int bc = (tid & 31) * 4;      // B col (e)

    const float Rv = g_R[(size_t)b * L_IN + l0 + lr];

    float acc[8][8] = {};

    for (int k0 = 0; k0 < L_ENC; k0 += BK) {
        float4 s = *reinterpret_cast<const float4*>(
            &g_scores[((size_t)b * L_IN + l0 + lr) * L_ENC + k0 + lk]);
        s.x = __fdiv_rn(s.x, Rv); s.y = __fdiv_rn(s.y, Rv);
        s.z = __fdiv_rn(s.z, Rv); s.w = __fdiv_rn(s.w, Rv);
        float4 e = *reinterpret_cast<const float4*>(
            &enc[((size_t)(k0 + br) * BATCH + b) * D + e0 + bc]);
        __syncthreads();
        As[lk + 0][lr] = s.x; As[lk + 1][lr] = s.y; As[lk + 2][lr] = s.z; As[lk + 3][lr] = s.w;
        *reinterpret_cast<float4*>(&Bs[br][bc]) = e;
        __syncthreads();
        GEMM_INNER(As, Bs, acc)
    }
#pragma unroll
    for (int i = 0; i < 8; ++i) {
        const int l = l0 + (i < 4 ? 4 * ty + i : 64 + 4 * ty + (i - 4));
        float* base = &g_ctx[((size_t)b * L_IN + l) * D + e0];
        float4 v0 = {acc[i][0], acc[i][1], acc[i][2], acc[i][3]};
        float4 v1 = {acc[i][4], acc[i][5], acc[i][6], acc[i][7]};
        *reinterpret_cast<float4*>(base + 4 * tx) = v0;
        *reinterpret_cast<float4*>(base + 64 + 4 * tx) = v1;
    }
}

// ---------------------------------------------------------------------------
// K5: out[(l*16+b)][i] = fl(asc-e FMA dot(ctx[b][l][:], W3[i][:]) + b3[i])
// A rows: r = b*1024+l (g_ctx natural). Output rows: l*16+b.
// ---------------------------------------------------------------------------
__global__ __launch_bounds__(256) void k_out(
    const float* __restrict__ W3, const float* __restrict__ b3,
    float* __restrict__ out)
{
    __shared__ float As[BK][TM], Bs[BK][TN];
    const int tid = threadIdx.x;
    const int tx = tid & 15, ty = tid >> 4;
    const int row0 = blockIdx.y * TM;
    const int col0 = blockIdx.x * TN;
    const int lr = tid >> 1;
    const int lk = (tid & 1) * 4;

    float acc[8][8] = {};

    for (int k0 = 0; k0 < D; k0 += BK) {
        float4 a = *reinterpret_cast<const float4*>(
            &g_ctx[(size_t)(row0 + lr) * D + k0 + lk]);
        float4 w = *reinterpret_cast<const float4*>(
            &W3[(size_t)(col0 + lr) * D + k0 + lk]);
        __syncthreads();
        As[lk + 0][lr] = a.x; As[lk + 1][lr] = a.y; As[lk + 2][lr] = a.z; As[lk + 3][lr] = a.w;
        Bs[lk + 0][lr] = w.x; Bs[lk + 1][lr] = w.y; Bs[lk + 2][lr] = w.z; Bs[lk + 3][lr] = w.w;
        __syncthreads();
        GEMM_INNER(As, Bs, acc)
    }
#pragma unroll
    for (int half = 0; half < 2; ++half) {
        const int cbase = col0 + 64 * half + 4 * tx;
        const float4 bb = *reinterpret_cast<const float4*>(&b3[cbase]);
        const float bv[4] = {bb.x, bb.y, bb.z, bb.w};
#pragma unroll
        for (int i = 0; i < 8; ++i) {
            const int r = row0 + (i < 4 ? 4 * ty + i : 64 + 4 * ty + (i - 4));
            const int b = r >> 10, l = r & (L_IN - 1);
            float4 v;
            v.x = acc[i][4 * half + 0] + bv[0];
            v.y = acc[i][4 * half + 1] + bv[1];
            v.z = acc[i][4 * half + 2] + bv[2];
            v.w = acc[i][4 * half + 3] + bv[3];
            *reinterpret_cast<float4*>(&out[((size_t)l * BATCH + b) * D + cbase]) = v;
        }
    }
}

// ---------------------------------------------------------------------------
extern "C" void kernel_launch(void* const* d_in, const int* in_sizes, int n_in,
                              void* d_out, int out_size)
{
    const float* in_seq   = (const float*)d_in[0];
    const float* enc_seq  = (const float*)d_in[1];
    const float* prev_tgt = (const float*)d_in[2];
    const float* W_in2enc = (const float*)d_in[3];
    const float* b_in2enc = (const float*)d_in[4];
    const float* W_lab2enc= (const float*)d_in[5];
    const float* b_lab2enc= (const float*)d_in[6];
    const float* W_enc2in = (const float*)d_in[7];
    const float* b_enc2in = (const float*)d_in[8];
    float* out = (float*)d_out;

    k_proj1  <<<dim3(D / TN, ROWS / TM), 256>>>(in_seq,   W_in2enc,  b_in2enc);
    k_proj2  <<<dim3(D / TN, ROWS / TM), 256>>>(prev_tgt, W_lab2enc, b_lab2enc);
    k_scores <<<dim3(L_ENC / TN, L_IN / TM, BATCH), 256>>>(enc_seq);
    k_rowsum <<<BATCH * L_IN / 8, 512>>>();
    k_context<<<dim3(D / TN, L_IN / TM, BATCH), 256>>>(enc_seq);
    k_out    <<<dim3(D / TN, ROWS / TM), 256>>>(W_enc2in, b_enc2in, out);
}

// round 12
// speedup vs baseline: 11.1701x; 1.0951x over previous
#include <cuda_runtime.h>
#include <cuda_bf16.h>
#include <cstdint>

#define L_IN  1024
#define L_ENC 1024
#define BATCH 16
#define D     512
#define ROWS  (L_IN * BATCH)   // 16384

#define TM 128
#define TN 128
#define BK 8

// Scratch (device globals)
__device__ float g_dvals[ROWS * D];                      // [b][l][e]
__device__ float g_scores[(size_t)BATCH * L_IN * L_ENC]; // [b][l][m]
__device__ float g_ctx[ROWS * D];                        // [b][l][e]
__device__ float g_R[BATCH * L_IN];                      // [b*1024+l]

// ---------------------------------------------------------------------------
// FROZEN SENSITIVE PATH (bit-identical to R10): proj1, proj2, scores, rowsum
// ---------------------------------------------------------------------------
#define GEMM_INNER(As, Bs, acc)                                              \
    _Pragma("unroll")                                                        \
    for (int kk = 0; kk < BK; ++kk) {                                        \
        float a[8], bb[8];                                                   \
        *reinterpret_cast<float4*>(&a[0])  = *reinterpret_cast<const float4*>(&As[kk][4 * ty]);       \
        *reinterpret_cast<float4*>(&a[4])  = *reinterpret_cast<const float4*>(&As[kk][64 + 4 * ty]);  \
        *reinterpret_cast<float4*>(&bb[0]) = *reinterpret_cast<const float4*>(&Bs[kk][4 * tx]);       \
        *reinterpret_cast<float4*>(&bb[4]) = *reinterpret_cast<const float4*>(&Bs[kk][64 + 4 * tx]);  \
        _Pragma("unroll")                                                    \
        for (int i = 0; i < 8; ++i)                                          \
            _Pragma("unroll")                                                \
            for (int j = 0; j < 8; ++j)                                      \
                acc[i][j] = fmaf(a[i], bb[j], acc[i][j]);                    \
    }

__global__ __launch_bounds__(256) void k_proj1(
    const float* __restrict__ A, const float* __restrict__ W,
    const float* __restrict__ bias)
{
    __shared__ float As[BK][TM], Bs[BK][TN];
    const int tid = threadIdx.x;
    const int tx = tid & 15, ty = tid >> 4;
    const int row0 = blockIdx.y * TM;
    const int col0 = blockIdx.x * TN;
    const int lr = tid >> 1;
    const int lk = (tid & 1) * 4;

    float acc[8][8] = {};

    for (int k0 = 0; k0 < D; k0 += BK) {
        float4 a = *reinterpret_cast<const float4*>(&A[(size_t)(row0 + lr) * D + k0 + lk]);
        float4 w = *reinterpret_cast<const float4*>(&W[(size_t)(col0 + lr) * D + k0 + lk]);
        __syncthreads();
        As[lk + 0][lr] = a.x; As[lk + 1][lr] = a.y; As[lk + 2][lr] = a.z; As[lk + 3][lr] = a.w;
        Bs[lk + 0][lr] = w.x; Bs[lk + 1][lr] = w.y; Bs[lk + 2][lr] = w.z; Bs[lk + 3][lr] = w.w;
        __syncthreads();
        GEMM_INNER(As, Bs, acc)
    }
#pragma unroll
    for (int half = 0; half < 2; ++half) {
        const int cbase = col0 + 64 * half + 4 * tx;
        const float4 bb = *reinterpret_cast<const float4*>(&bias[cbase]);
        const float bv[4] = {bb.x, bb.y, bb.z, bb.w};
#pragma unroll
        for (int i = 0; i < 8; ++i) {
            const int r = row0 + (i < 4 ? 4 * ty + i : 64 + 4 * ty + (i - 4));
            const int b = r & 15, l = r >> 4;
            float4 v;
            v.x = acc[i][4 * half + 0] + bv[0];
            v.y = acc[i][4 * half + 1] + bv[1];
            v.z = acc[i][4 * half + 2] + bv[2];
            v.w = acc[i][4 * half + 3] + bv[3];
            *reinterpret_cast<float4*>(&g_dvals[((size_t)b * L_IN + l) * D + cbase]) = v;
        }
    }
}

__global__ __launch_bounds__(256) void k_proj2(
    const float* __restrict__ A, const float* __restrict__ W,
    const float* __restrict__ bias)
{
    __shared__ float As[BK][TM], Bs[BK][TN];
    const int tid = threadIdx.x;
    const int tx = tid & 15, ty = tid >> 4;
    const int row0 = blockIdx.y * TM;
    const int col0 = blockIdx.x * TN;
    const int lr = tid >> 1;
    const int lk = (tid & 1) * 4;

    float acc[8][8] = {};

    for (int k0 = 0; k0 < D; k0 += BK) {
        float4 a = *reinterpret_cast<const float4*>(&A[(size_t)(row0 + lr) * D + k0 + lk]);
        float4 w = *reinterpret_cast<const float4*>(&W[(size_t)(col0 + lr) * D + k0 + lk]);
        __syncthreads();
        As[lk + 0][lr] = a.x; As[lk + 1][lr] = a.y; As[lk + 2][lr] = a.z; As[lk + 3][lr] = a.w;
        Bs[lk + 0][lr] = w.x; Bs[lk + 1][lr] = w.y; Bs[lk + 2][lr] = w.z; Bs[lk + 3][lr] = w.w;
        __syncthreads();
        GEMM_INNER(As, Bs, acc)
    }
#pragma unroll
    for (int half = 0; half < 2; ++half) {
        const int cbase = col0 + 64 * half + 4 * tx;
        const float4 bb = *reinterpret_cast<const float4*>(&bias[cbase]);
        const float bv[4] = {bb.x, bb.y, bb.z, bb.w};
#pragma unroll
        for (int i = 0; i < 8; ++i) {
            const int r = row0 + (i < 4 ? 4 * ty + i : 64 + 4 * ty + (i - 4));
            const int b = r & 15, l = r >> 4;
            float* dst = &g_dvals[((size_t)b * L_IN + l) * D + cbase];
            float4 prev = *reinterpret_cast<const float4*>(dst);
            float4 v;
            v.x = prev.x + (acc[i][4 * half + 0] + bv[0]);
            v.y = prev.y + (acc[i][4 * half + 1] + bv[1]);
            v.z = prev.z + (acc[i][4 * half + 2] + bv[2]);
            v.w = prev.w + (acc[i][4 * half + 3] + bv[3]);
            *reinterpret_cast<float4*>(dst) = v;
        }
    }
}

__global__ __launch_bounds__(256) void k_scores(const float* __restrict__ enc)
{
    __shared__ float As[BK][TM], Bs[BK][TN];
    const int tid = threadIdx.x;
    const int tx = tid & 15, ty = tid >> 4;
    const int l0 = blockIdx.y * TM;
    const int m0 = blockIdx.x * TN;
    const int b  = blockIdx.z;
    const int lr = tid >> 1;
    const int lk = (tid & 1) * 4;

    float acc[8][8] = {};

    for (int k0 = 0; k0 < D; k0 += BK) {
        float4 a = *reinterpret_cast<const float4*>(
            &g_dvals[((size_t)b * L_IN + l0 + lr) * D + k0 + lk]);
        float4 e = *reinterpret_cast<const float4*>(
            &enc[((size_t)(m0 + lr) * BATCH + b) * D + k0 + lk]);
        __syncthreads();
        As[lk + 0][lr] = a.x; As[lk + 1][lr] = a.y; As[lk + 2][lr] = a.z; As[lk + 3][lr] = a.w;
        Bs[lk + 0][lr] = e.x; Bs[lk + 1][lr] = e.y; Bs[lk + 2][lr] = e.z; Bs[lk + 3][lr] = e.w;
        __syncthreads();
        GEMM_INNER(As, Bs, acc)
    }
#pragma unroll
    for (int i = 0; i < 8; ++i) {
        const int l = l0 + (i < 4 ? 4 * ty + i : 64 + 4 * ty + (i - 4));
        float* base = &g_scores[((size_t)b * L_IN + l) * L_ENC + m0];
        float4 v0 = {acc[i][0], acc[i][1], acc[i][2], acc[i][3]};
        float4 v1 = {acc[i][4], acc[i][5], acc[i][6], acc[i][7]};
        *reinterpret_cast<float4*>(base + 4 * tx) = v0;
        *reinterpret_cast<float4*>(base + 64 + 4 * tx) = v1;
    }
}

__global__ __launch_bounds__(512) void k_rowsum()
{
    __shared__ float warp_part[16];
    const int tid = threadIdx.x;
    const int row0 = blockIdx.x * 8;
    const int j = tid >> 6;
    const int t = tid & 63;
    const float* sr = g_scores + (size_t)(row0 + j) * L_ENC;
    float a = 0.f;
#pragma unroll
    for (int i = 0; i < 16; ++i)
        a += sr[t + (i << 6)];
#pragma unroll
    for (int o = 16; o; o >>= 1)
        a += __shfl_down_sync(0xFFFFFFFFu, a, o);
    if ((t & 31) == 0)
        warp_part[tid >> 5] = a;
    __syncthreads();
    if (tid < 8)
        g_R[row0 + tid] = warp_part[2 * tid] + warp_part[2 * tid + 1];
}

// ---------------------------------------------------------------------------
// INSENSITIVE NUMERATOR — TF32x3 tensor-core GEMMs (context, out)
// x = hi + lo (tf32 each); D += hi*hi + hi*lo + lo*hi  → ~2^-22 relative.
// Block 128x128, 8 warps, warp tile 64x32 = 4x4 m16n8 mma tiles, k-block 16.
// ---------------------------------------------------------------------------
__device__ __forceinline__ void tf32_split(float x, uint32_t& hi, uint32_t& lo) {
    uint32_t h;
    asm("cvt.rna.tf32.f32 %0, %1;" : "=r"(h) : "f"(x));
    const float r = x - __uint_as_float(h);
    asm("cvt.rna.tf32.f32 %0, %1;" : "=r"(lo) : "f"(r));
    hi = h;
}

__device__ __forceinline__ void mma_tf32(float* c, const uint32_t* a, const uint32_t* b) {
    asm volatile(
        "mma.sync.aligned.m16n8k8.row.col.f32.tf32.tf32.f32 "
        "{%0,%1,%2,%3}, {%4,%5,%6,%7}, {%8,%9}, {%0,%1,%2,%3};"
        : "+f"(c[0]), "+f"(c[1]), "+f"(c[2]), "+f"(c[3])
        : "r"(a[0]), "r"(a[1]), "r"(a[2]), "r"(a[3]), "r"(b[0]), "r"(b[1]));
}

// K4tc: g_ctx[b][l][e] = sum_m (scores[b][l][m] * (1/R[b][l])) * enc[m][b][e]
__global__ __launch_bounds__(256) void k_ctx_tc(const float* __restrict__ enc)
{
    __shared__ uint32_t Ah[16][132], Al[16][132], Bh[16][132], Bl[16][132];
    const int tid  = threadIdx.x;
    const int lane = tid & 31, warp = tid >> 5;
    const int wy = warp & 1, wx = warp >> 1;   // warp origin (64*wy, 32*wx)
    const int e0 = blockIdx.x * 128;
    const int l0 = blockIdx.y * 128;
    const int b  = blockIdx.z;

    const int ar  = tid >> 2;            // A stage row 0..63 (and +64)
    const int akc = (tid & 3) * 4;       // A stage k offset
    const int bkr = tid >> 4;            // B stage k row 0..15
    const int bec = (tid & 15) * 8;      // B stage col offset

    const float inv0 = __fdiv_rn(1.f, g_R[b * L_IN + l0 + ar]);
    const float inv1 = __fdiv_rn(1.f, g_R[b * L_IN + l0 + ar + 64]);

    float acc[4][4][4] = {};

    for (int k0 = 0; k0 < L_ENC; k0 += 16) {
        float4 sa0 = *reinterpret_cast<const float4*>(
            &g_scores[((size_t)b * L_IN + l0 + ar) * L_ENC + k0 + akc]);
        float4 sa1 = *reinterpret_cast<const float4*>(
            &g_scores[((size_t)b * L_IN + l0 + ar + 64) * L_ENC + k0 + akc]);
        float4 eb0 = *reinterpret_cast<const float4*>(
            &enc[((size_t)(k0 + bkr) * BATCH + b) * D + e0 + bec]);
        float4 eb1 = *reinterpret_cast<const float4*>(
            &enc[((size_t)(k0 + bkr) * BATCH + b) * D + e0 + bec + 4]);
        __syncthreads();
        {
            float v0[4] = {sa0.x * inv0, sa0.y * inv0, sa0.z * inv0, sa0.w * inv0};
            float v1[4] = {sa1.x * inv1, sa1.y * inv1, sa1.z * inv1, sa1.w * inv1};
#pragma unroll
            for (int j = 0; j < 4; ++j) {
                uint32_t h, l;
                tf32_split(v0[j], h, l); Ah[akc + j][ar] = h;      Al[akc + j][ar] = l;
                tf32_split(v1[j], h, l); Ah[akc + j][ar + 64] = h; Al[akc + j][ar + 64] = l;
            }
            const float w[8] = {eb0.x, eb0.y, eb0.z, eb0.w, eb1.x, eb1.y, eb1.z, eb1.w};
#pragma unroll
            for (int j = 0; j < 8; ++j) {
                uint32_t h, l;
                tf32_split(w[j], h, l); Bh[bkr][bec + j] = h; Bl[bkr][bec + j] = l;
            }
        }
        __syncthreads();
#pragma unroll
        for (int ks = 0; ks < 2; ++ks) {
            const int k8 = ks * 8;
            const int fr = lane >> 2, fc = lane & 3;
            uint32_t ah[4][4], al[4][4], bh[4][2], bl[4][2];
#pragma unroll
            for (int mt = 0; mt < 4; ++mt) {
                const int mb = wy * 64 + mt * 16;
                ah[mt][0] = Ah[k8 + fc][mb + fr];     al[mt][0] = Al[k8 + fc][mb + fr];
                ah[mt][1] = Ah[k8 + fc][mb + fr + 8]; al[mt][1] = Al[k8 + fc][mb + fr + 8];
                ah[mt][2] = Ah[k8 + fc + 4][mb + fr];     al[mt][2] = Al[k8 + fc + 4][mb + fr];
                ah[mt][3] = Ah[k8 + fc + 4][mb + fr + 8]; al[mt][3] = Al[k8 + fc + 4][mb + fr + 8];
            }
#pragma unroll
            for (int nt = 0; nt < 4; ++nt) {
                const int nb = wx * 32 + nt * 8;
                bh[nt][0] = Bh[k8 + fc][nb + fr];     bl[nt][0] = Bl[k8 + fc][nb + fr];
                bh[nt][1] = Bh[k8 + fc + 4][nb + fr]; bl[nt][1] = Bl[k8 + fc + 4][nb + fr];
            }
#pragma unroll
            for (int mt = 0; mt < 4; ++mt)
#pragma unroll
                for (int nt = 0; nt < 4; ++nt) {
                    mma_tf32(acc[mt][nt], ah[mt], bl[nt]);
                    mma_tf32(acc[mt][nt], al[mt], bh[nt]);
                    mma_tf32(acc[mt][nt], ah[mt], bh[nt]);
                }
        }
    }
    const int fr = lane >> 2, fc = lane & 3;
#pragma unroll
    for (int mt = 0; mt < 4; ++mt)
#pragma unroll
        for (int nt = 0; nt < 4; ++nt) {
            const int row = l0 + wy * 64 + mt * 16 + fr;
            const int col = e0 + wx * 32 + nt * 8 + 2 * fc;
            float2 v0 = {acc[mt][nt][0], acc[mt][nt][1]};
            float2 v1 = {acc[mt][nt][2], acc[mt][nt][3]};
            *reinterpret_cast<float2*>(&g_ctx[((size_t)b * L_IN + row) * D + col]) = v0;
            *reinterpret_cast<float2*>(&g_ctx[((size_t)b * L_IN + row + 8) * D + col]) = v1;
        }
}

// K5tc: out[(l*16+b)][i] = sum_e ctx[b][l][e] * W3[i][e] + b3[i]
__global__ __launch_bounds__(256) void k_out_tc(
    const float* __restrict__ W3, const float* __restrict__ b3,
    float* __restrict__ out)
{
    __shared__ uint32_t Ah[16][132], Al[16][132], Bh[16][132], Bl[16][132];
    const int tid  = threadIdx.x;
    const int lane = tid & 31, warp = tid >> 5;
    const int wy = warp & 1, wx = warp >> 1;
    const int col0 = blockIdx.x * 128;
    const int row0 = blockIdx.y * 128;   // rows r = b*1024 + l (g_ctx order)

    const int ar  = tid >> 2;
    const int akc = (tid & 3) * 4;
    const int bnr = tid >> 1;            // B stage n row 0..127
    const int bkc = (tid & 1) * 8;       // B stage k offset

    float acc[4][4][4] = {};

    for (int k0 = 0; k0 < D; k0 += 16) {
        float4 a0 = *reinterpret_cast<const float4*>(
            &g_ctx[(size_t)(row0 + ar) * D + k0 + akc]);
        float4 a1 = *reinterpret_cast<const float4*>(
            &g_ctx[(size_t)(row0 + ar + 64) * D + k0 + akc]);
        float4 w0 = *reinterpret_cast<const float4*>(
            &W3[(size_t)(col0 + bnr) * D + k0 + bkc]);
        float4 w1 = *reinterpret_cast<const float4*>(
            &W3[(size_t)(col0 + bnr) * D + k0 + bkc + 4]);
        __syncthreads();
        {
            const float va0[4] = {a0.x, a0.y, a0.z, a0.w};
            const float va1[4] = {a1.x, a1.y, a1.z, a1.w};
#pragma unroll
            for (int j = 0; j < 4; ++j) {
                uint32_t h, l;
                tf32_split(va0[j], h, l); Ah[akc + j][ar] = h;      Al[akc + j][ar] = l;
                tf32_split(va1[j], h, l); Ah[akc + j][ar + 64] = h; Al[akc + j][ar + 64] = l;
            }
            const float w[8] = {w0.x, w0.y, w0.z, w0.w, w1.x, w1.y, w1.z, w1.w};
#pragma unroll
            for (int j = 0; j < 8; ++j) {
                uint32_t h, l;
                tf32_split(w[j], h, l); Bh[bkc + j][bnr] = h; Bl[bkc + j][bnr] = l;
            }
        }
        __syncthreads();
#pragma unroll
        for (int ks = 0; ks < 2; ++ks) {
            const int k8 = ks * 8;
            const int fr = lane >> 2, fc = lane & 3;
            uint32_t ah[4][4], al[4][4], bh[4][2], bl[4][2];
#pragma unroll
            for (int mt = 0; mt < 4; ++mt) {
                const int mb = wy * 64 + mt * 16;
                ah[mt][0] = Ah[k8 + fc][mb + fr];     al[mt][0] = Al[k8 + fc][mb + fr];
                ah[mt][1] = Ah[k8 + fc][mb + fr + 8]; al[mt][1] = Al[k8 + fc][mb + fr + 8];
                ah[mt][2] = Ah[k8 + fc + 4][mb + fr];     al[mt][2] = Al[k8 + fc + 4][mb + fr];
                ah[mt][3] = Ah[k8 + fc + 4][mb + fr + 8]; al[mt][3] = Al[k8 + fc + 4][mb + fr + 8];
            }
#pragma unroll
            for (int nt = 0; nt < 4; ++nt) {
                const int nb = wx * 32 + nt * 8;
                bh[nt][0] = Bh[k8 + fc][nb + fr];     bl[nt][0] = Bl[k8 + fc][nb + fr];
                bh[nt][1] = Bh[k8 + fc + 4][nb + fr]; bl[nt][1] = Bl[k8 + fc + 4][nb + fr];
            }
#pragma unroll
            for (int mt = 0; mt < 4; ++mt)
#pragma unroll
                for (int nt = 0; nt < 4; ++nt) {
                    mma_tf32(acc[mt][nt], ah[mt], bl[nt]);
                    mma_tf32(acc[mt][nt], al[mt], bh[nt]);
                    mma_tf32(acc[mt][nt], ah[mt], bh[nt]);
                }
        }
    }
    const int fr = lane >> 2, fc = lane & 3;
#pragma unroll
    for (int mt = 0; mt < 4; ++mt)
#pragma unroll
        for (int nt = 0; nt < 4; ++nt) {
            const int col = col0 + wx * 32 + nt * 8 + 2 * fc;
            const float bx = b3[col], by = b3[col + 1];
#pragma unroll
            for (int h = 0; h < 2; ++h) {
                const int r = row0 + wy * 64 + mt * 16 + fr + 8 * h;
                const int b = r >> 10, l = r & (L_IN - 1);
                float2 v = {acc[mt][nt][2 * h] + bx, acc[mt][nt][2 * h + 1] + by};
                *reinterpret_cast<float2*>(&out[((size_t)l * BATCH + b) * D + col]) = v;
            }
        }
}

// ---------------------------------------------------------------------------
extern "C" void kernel_launch(void* const* d_in, const int* in_sizes, int n_in,
                              void* d_out, int out_size)
{
    const float* in_seq   = (const float*)d_in[0];
    const float* enc_seq  = (const float*)d_in[1];
    const float* prev_tgt = (const float*)d_in[2];
    const float* W_in2enc = (const float*)d_in[3];
    const float* b_in2enc = (const float*)d_in[4];
    const float* W_lab2enc= (const float*)d_in[5];
    const float* b_lab2enc= (const float*)d_in[6];
    const float* W_enc2in = (const float*)d_in[7];
    const float* b_enc2in = (const float*)d_in[8];
    float* out = (float*)d_out;

    k_proj1  <<<dim3(D / TN, ROWS / TM), 256>>>(in_seq,   W_in2enc,  b_in2enc);
    k_proj2  <<<dim3(D / TN, ROWS / TM), 256>>>(prev_tgt, W_lab2enc, b_lab2enc);
    k_scores <<<dim3(L_ENC / TN, L_IN / TM, BATCH), 256>>>(enc_seq);
    k_rowsum <<<BATCH * L_IN / 8, 512>>>();
    k_ctx_tc <<<dim3(D / 128, L_IN / 128, BATCH), 256>>>(enc_seq);
    k_out_tc <<<dim3(D / 128, ROWS / 128), 256>>>(W_enc2in, b_enc2in, out);
}

// round 13
// speedup vs baseline: 11.4886x; 1.0285x over previous
#include <cuda_runtime.h>
#include <cuda_bf16.h>
#include <cstdint>

#define L_IN  1024
#define L_ENC 1024
#define BATCH 16
#define D     512
#define ROWS  (L_IN * BATCH)   // 16384

#define TM 128
#define TN 128
#define BK 8

typedef unsigned long long u64;

// Scratch (device globals)
__device__ float g_dvals[ROWS * D];                      // [b][l][e]
__device__ float g_scores[(size_t)BATCH * L_IN * L_ENC]; // [b][l][m]
__device__ float g_ctx[ROWS * D];                        // [b][l][e]
__device__ float g_R[BATCH * L_IN];                      // [b*1024+l]

// ---------------------------------------------------------------------------
// Packed f32x2 helpers — each 32-bit lane is an IEEE fp32 RN FMA, bit-identical
// to scalar fmaf. Packing pairs outputs (j, j+1); per-output ascending-k
// single-accumulator order is unchanged → frozen arithmetic preserved.
// ---------------------------------------------------------------------------
__device__ __forceinline__ u64 fma2(u64 a, u64 b, u64 c) {
    u64 d;
    asm("fma.rn.f32x2 %0, %1, %2, %3;" : "=l"(d) : "l"(a), "l"(b), "l"(c));
    return d;
}
__device__ __forceinline__ u64 pack2(float x) {
    u64 d;
    asm("mov.b64 %0, {%1, %1};" : "=l"(d) : "f"(x));
    return d;
}
__device__ __forceinline__ float2 unpack2(u64 v) {
    float2 r;
    asm("mov.b64 {%0, %1}, %2;" : "=f"(r.x), "=f"(r.y) : "l"(v));
    return r;
}

// FFMA2 GEMM inner: 32 fma.f32x2 + 8 packs per k-step (vs 64 FFMA).
#define GEMM_INNER2(As, Bs, acc2)                                            \
    _Pragma("unroll")                                                        \
    for (int kk = 0; kk < BK; ++kk) {                                        \
        float a[8];                                                          \
        *reinterpret_cast<float4*>(&a[0]) = *reinterpret_cast<const float4*>(&As[kk][4 * ty]);      \
        *reinterpret_cast<float4*>(&a[4]) = *reinterpret_cast<const float4*>(&As[kk][64 + 4 * ty]); \
        u64 bp[4];                                                           \
        *reinterpret_cast<ulonglong2*>(&bp[0]) = *reinterpret_cast<const ulonglong2*>(&Bs[kk][4 * tx]);      \
        *reinterpret_cast<ulonglong2*>(&bp[2]) = *reinterpret_cast<const ulonglong2*>(&Bs[kk][64 + 4 * tx]); \
        _Pragma("unroll")                                                    \
        for (int i = 0; i < 8; ++i) {                                        \
            const u64 ad = pack2(a[i]);                                      \
            _Pragma("unroll")                                                \
            for (int jp = 0; jp < 4; ++jp)                                   \
                acc2[i][jp] = fma2(ad, bp[jp], acc2[i][jp]);                 \
        }                                                                    \
    }
// acc2[i][0]=(j0,j1) acc2[i][1]=(j2,j3): cols 4tx+0..3
// acc2[i][2]=(j4,j5) acc2[i][3]=(j6,j7): cols 64+4tx+0..3

// ---------------------------------------------------------------------------
// K1a: g_dvals[b][l][e] = fl(asc_dot(in_row, W1[e]) + b1[e])
// ---------------------------------------------------------------------------
__global__ __launch_bounds__(256) void k_proj1(
    const float* __restrict__ A, const float* __restrict__ W,
    const float* __restrict__ bias)
{
    __shared__ __align__(16) float As[BK][TM], Bs[BK][TN];
    const int tid = threadIdx.x;
    const int tx = tid & 15, ty = tid >> 4;
    const int row0 = blockIdx.y * TM;
    const int col0 = blockIdx.x * TN;
    const int lr = tid >> 1;
    const int lk = (tid & 1) * 4;

    u64 acc2[8][4] = {};

    for (int k0 = 0; k0 < D; k0 += BK) {
        float4 a = *reinterpret_cast<const float4*>(&A[(size_t)(row0 + lr) * D + k0 + lk]);
        float4 w = *reinterpret_cast<const float4*>(&W[(size_t)(col0 + lr) * D + k0 + lk]);
        __syncthreads();
        As[lk + 0][lr] = a.x; As[lk + 1][lr] = a.y; As[lk + 2][lr] = a.z; As[lk + 3][lr] = a.w;
        Bs[lk + 0][lr] = w.x; Bs[lk + 1][lr] = w.y; Bs[lk + 2][lr] = w.z; Bs[lk + 3][lr] = w.w;
        __syncthreads();
        GEMM_INNER2(As, Bs, acc2)
    }
#pragma unroll
    for (int half = 0; half < 2; ++half) {
        const int cbase = col0 + 64 * half + 4 * tx;
        const float4 bb = *reinterpret_cast<const float4*>(&bias[cbase]);
        const float bv[4] = {bb.x, bb.y, bb.z, bb.w};
#pragma unroll
        for (int i = 0; i < 8; ++i) {
            const int r = row0 + (i < 4 ? 4 * ty + i : 64 + 4 * ty + (i - 4));
            const int b = r & 15, l = r >> 4;
            const float2 c01 = unpack2(acc2[i][2 * half]);
            const float2 c23 = unpack2(acc2[i][2 * half + 1]);
            float4 v;
            v.x = c01.x + bv[0];
            v.y = c01.y + bv[1];
            v.z = c23.x + bv[2];
            v.w = c23.y + bv[3];
            *reinterpret_cast<float4*>(&g_dvals[((size_t)b * L_IN + l) * D + cbase]) = v;
        }
    }
}

// ---------------------------------------------------------------------------
// K1b: g_dvals += fl(asc_dot(tgt_row, W2[e]) + b2[e])   (bitwise == fused)
// ---------------------------------------------------------------------------
__global__ __launch_bounds__(256) void k_proj2(
    const float* __restrict__ A, const float* __restrict__ W,
    const float* __restrict__ bias)
{
    __shared__ __align__(16) float As[BK][TM], Bs[BK][TN];
    const int tid = threadIdx.x;
    const int tx = tid & 15, ty = tid >> 4;
    const int row0 = blockIdx.y * TM;
    const int col0 = blockIdx.x * TN;
    const int lr = tid >> 1;
    const int lk = (tid & 1) * 4;

    u64 acc2[8][4] = {};

    for (int k0 = 0; k0 < D; k0 += BK) {
        float4 a = *reinterpret_cast<const float4*>(&A[(size_t)(row0 + lr) * D + k0 + lk]);
        float4 w = *reinterpret_cast<const float4*>(&W[(size_t)(col0 + lr) * D + k0 + lk]);
        __syncthreads();
        As[lk + 0][lr] = a.x; As[lk + 1][lr] = a.y; As[lk + 2][lr] = a.z; As[lk + 3][lr] = a.w;
        Bs[lk + 0][lr] = w.x; Bs[lk + 1][lr] = w.y; Bs[lk + 2][lr] = w.z; Bs[lk + 3][lr] = w.w;
        __syncthreads();
        GEMM_INNER2(As, Bs, acc2)
    }
#pragma unroll
    for (int half = 0; half < 2; ++half) {
        const int cbase = col0 + 64 * half + 4 * tx;
        const float4 bb = *reinterpret_cast<const float4*>(&bias[cbase]);
        const float bv[4] = {bb.x, bb.y, bb.z, bb.w};
#pragma unroll
        for (int i = 0; i < 8; ++i) {
            const int r = row0 + (i < 4 ? 4 * ty + i : 64 + 4 * ty + (i - 4));
            const int b = r & 15, l = r >> 4;
            float* dst = &g_dvals[((size_t)b * L_IN + l) * D + cbase];
            float4 prev = *reinterpret_cast<const float4*>(dst);
            const float2 c01 = unpack2(acc2[i][2 * half]);
            const float2 c23 = unpack2(acc2[i][2 * half + 1]);
            float4 v;
            v.x = prev.x + (c01.x + bv[0]);
            v.y = prev.y + (c01.y + bv[1]);
            v.z = prev.z + (c23.x + bv[2]);
            v.w = prev.w + (c23.y + bv[3]);
            *reinterpret_cast<float4*>(dst) = v;
        }
    }
}

// ---------------------------------------------------------------------------
// K2: scores[b][l][m] = asc-e FMA dot(d_vals[b][l][:], enc[m][b][:])
// ---------------------------------------------------------------------------
__global__ __launch_bounds__(256) void k_scores(const float* __restrict__ enc)
{
    __shared__ __align__(16) float As[BK][TM], Bs[BK][TN];
    const int tid = threadIdx.x;
    const int tx = tid & 15, ty = tid >> 4;
    const int l0 = blockIdx.y * TM;
    const int m0 = blockIdx.x * TN;
    const int b  = blockIdx.z;
    const int lr = tid >> 1;
    const int lk = (tid & 1) * 4;

    u64 acc2[8][4] = {};

    for (int k0 = 0; k0 < D; k0 += BK) {
        float4 a = *reinterpret_cast<const float4*>(
            &g_dvals[((size_t)b * L_IN + l0 + lr) * D + k0 + lk]);
        float4 e = *reinterpret_cast<const float4*>(
            &enc[((size_t)(m0 + lr) * BATCH + b) * D + k0 + lk]);
        __syncthreads();
        As[lk + 0][lr] = a.x; As[lk + 1][lr] = a.y; As[lk + 2][lr] = a.z; As[lk + 3][lr] = a.w;
        Bs[lk + 0][lr] = e.x; Bs[lk + 1][lr] = e.y; Bs[lk + 2][lr] = e.z; Bs[lk + 3][lr] = e.w;
        __syncthreads();
        GEMM_INNER2(As, Bs, acc2)
    }
#pragma unroll
    for (int i = 0; i < 8; ++i) {
        const int l = l0 + (i < 4 ? 4 * ty + i : 64 + 4 * ty + (i - 4));
        float* base = &g_scores[((size_t)b * L_IN + l) * L_ENC + m0];
        const float2 p0 = unpack2(acc2[i][0]);
        const float2 p1 = unpack2(acc2[i][1]);
        const float2 p2 = unpack2(acc2[i][2]);
        const float2 p3 = unpack2(acc2[i][3]);
        float4 v0 = {p0.x, p0.y, p1.x, p1.y};
        float4 v1 = {p2.x, p2.y, p3.x, p3.y};
        *reinterpret_cast<float4*>(base + 4 * tx) = v0;
        *reinterpret_cast<float4*>(base + 64 + 4 * tx) = v1;
    }
}

// ---------------------------------------------------------------------------
// K3: rowsum — FROZEN XLA row-reduce emulation (bit-identical to R5/R10).
// ---------------------------------------------------------------------------
__global__ __launch_bounds__(512) void k_rowsum()
{
    __shared__ float warp_part[16];
    const int tid = threadIdx.x;
    const int row0 = blockIdx.x * 8;
    const int j = tid >> 6;
    const int t = tid & 63;
    const float* sr = g_scores + (size_t)(row0 + j) * L_ENC;
    float a = 0.f;
#pragma unroll
    for (int i = 0; i < 16; ++i)
        a += sr[t + (i << 6)];
#pragma unroll
    for (int o = 16; o; o >>= 1)
        a += __shfl_down_sync(0xFFFFFFFFu, a, o);
    if ((t & 31) == 0)
        warp_part[tid >> 5] = a;
    __syncthreads();
    if (tid < 8)
        g_R[row0 + tid] = warp_part[2 * tid] + warp_part[2 * tid + 1];
}

// ---------------------------------------------------------------------------
// INSENSITIVE NUMERATOR — TF32x3 tensor-core GEMMs (unchanged from R12)
// ---------------------------------------------------------------------------
__device__ __forceinline__ void tf32_split(float x, uint32_t& hi, uint32_t& lo) {
    uint32_t h;
    asm("cvt.rna.tf32.f32 %0, %1;" : "=r"(h) : "f"(x));
    const float r = x - __uint_as_float(h);
    asm("cvt.rna.tf32.f32 %0, %1;" : "=r"(lo) : "f"(r));
    hi = h;
}

__device__ __forceinline__ void mma_tf32(float* c, const uint32_t* a, const uint32_t* b) {
    asm volatile(
        "mma.sync.aligned.m16n8k8.row.col.f32.tf32.tf32.f32 "
        "{%0,%1,%2,%3}, {%4,%5,%6,%7}, {%8,%9}, {%0,%1,%2,%3};"
        : "+f"(c[0]), "+f"(c[1]), "+f"(c[2]), "+f"(c[3])
        : "r"(a[0]), "r"(a[1]), "r"(a[2]), "r"(a[3]), "r"(b[0]), "r"(b[1]));
}

__global__ __launch_bounds__(256) void k_ctx_tc(const float* __restrict__ enc)
{
    __shared__ uint32_t Ah[16][132], Al[16][132], Bh[16][132], Bl[16][132];
    const int tid  = threadIdx.x;
    const int lane = tid & 31, warp = tid >> 5;
    const int wy = warp & 1, wx = warp >> 1;
    const int e0 = blockIdx.x * 128;
    const int l0 = blockIdx.y * 128;
    const int b  = blockIdx.z;

    const int ar  = tid >> 2;
    const int akc = (tid & 3) * 4;
    const int bkr = tid >> 4;
    const int bec = (tid & 15) * 8;

    const float inv0 = __fdiv_rn(1.f, g_R[b * L_IN + l0 + ar]);
    const float inv1 = __fdiv_rn(1.f, g_R[b * L_IN + l0 + ar + 64]);

    float acc[4][4][4] = {};

    for (int k0 = 0; k0 < L_ENC; k0 += 16) {
        float4 sa0 = *reinterpret_cast<const float4*>(
            &g_scores[((size_t)b * L_IN + l0 + ar) * L_ENC + k0 + akc]);
        float4 sa1 = *reinterpret_cast<const float4*>(
            &g_scores[((size_t)b * L_IN + l0 + ar + 64) * L_ENC + k0 + akc]);
        float4 eb0 = *reinterpret_cast<const float4*>(
            &enc[((size_t)(k0 + bkr) * BATCH + b) * D + e0 + bec]);
        float4 eb1 = *reinterpret_cast<const float4*>(
            &enc[((size_t)(k0 + bkr) * BATCH + b) * D + e0 + bec + 4]);
        __syncthreads();
        {
            float v0[4] = {sa0.x * inv0, sa0.y * inv0, sa0.z * inv0, sa0.w * inv0};
            float v1[4] = {sa1.x * inv1, sa1.y * inv1, sa1.z * inv1, sa1.w * inv1};
#pragma unroll
            for (int j = 0; j < 4; ++j) {
                uint32_t h, l;
                tf32_split(v0[j], h, l); Ah[akc + j][ar] = h;      Al[akc + j][ar] = l;
                tf32_split(v1[j], h, l); Ah[akc + j][ar + 64] = h; Al[akc + j][ar + 64] = l;
            }
            const float w[8] = {eb0.x, eb0.y, eb0.z, eb0.w, eb1.x, eb1.y, eb1.z, eb1.w};
#pragma unroll
            for (int j = 0; j < 8; ++j) {
                uint32_t h, l;
                tf32_split(w[j], h, l); Bh[bkr][bec + j] = h; Bl[bkr][bec + j] = l;
            }
        }
        __syncthreads();
#pragma unroll
        for (int ks = 0; ks < 2; ++ks) {
            const int k8 = ks * 8;
            const int fr = lane >> 2, fc = lane & 3;
            uint32_t ah[4][4], al[4][4], bh[4][2], bl[4][2];
#pragma unroll
            for (int mt = 0; mt < 4; ++mt) {
                const int mb = wy * 64 + mt * 16;
                ah[mt][0] = Ah[k8 + fc][mb + fr];     al[mt][0] = Al[k8 + fc][mb + fr];
                ah[mt][1] = Ah[k8 + fc][mb + fr + 8]; al[mt][1] = Al[k8 + fc][mb + fr + 8];
                ah[mt][2] = Ah[k8 + fc + 4][mb + fr];     al[mt][2] = Al[k8 + fc + 4][mb + fr];
                ah[mt][3] = Ah[k8 + fc + 4][mb + fr + 8]; al[mt][3] = Al[k8 + fc + 4][mb + fr + 8];
            }
#pragma unroll
            for (int nt = 0; nt < 4; ++nt) {
                const int nb = wx * 32 + nt * 8;
                bh[nt][0] = Bh[k8 + fc][nb + fr];     bl[nt][0] = Bl[k8 + fc][nb + fr];
                bh[nt][1] = Bh[k8 + fc + 4][nb + fr]; bl[nt][1] = Bl[k8 + fc + 4][nb + fr];
            }
#pragma unroll
            for (int mt = 0; mt < 4; ++mt)
#pragma unroll
                for (int nt = 0; nt < 4; ++nt) {
                    mma_tf32(acc[mt][nt], ah[mt], bl[nt]);
                    mma_tf32(acc[mt][nt], al[mt], bh[nt]);
                    mma_tf32(acc[mt][nt], ah[mt], bh[nt]);
                }
        }
    }
    const int fr = lane >> 2, fc = lane & 3;
#pragma unroll
    for (int mt = 0; mt < 4; ++mt)
#pragma unroll
        for (int nt = 0; nt < 4; ++nt) {
            const int row = l0 + wy * 64 + mt * 16 + fr;
            const int col = e0 + wx * 32 + nt * 8 + 2 * fc;
            float2 v0 = {acc[mt][nt][0], acc[mt][nt][1]};
            float2 v1 = {acc[mt][nt][2], acc[mt][nt][3]};
            *reinterpret_cast<float2*>(&g_ctx[((size_t)b * L_IN + row) * D + col]) = v0;
            *reinterpret_cast<float2*>(&g_ctx[((size_t)b * L_IN + row + 8) * D + col]) = v1;
        }
}

__global__ __launch_bounds__(256) void k_out_tc(
    const float* __restrict__ W3, const float* __restrict__ b3,
    float* __restrict__ out)
{
    __shared__ uint32_t Ah[16][132], Al[16][132], Bh[16][132], Bl[16][132];
    const int tid  = threadIdx.x;
    const int lane = tid & 31, warp = tid >> 5;
    const int wy = warp & 1, wx = warp >> 1;
    const int col0 = blockIdx.x * 128;
    const int row0 = blockIdx.y * 128;

    const int ar  = tid >> 2;
    const int akc = (tid & 3) * 4;
    const int bnr = tid >> 1;
    const int bkc = (tid & 1) * 8;

    float acc[4][4][4] = {};

    for (int k0 = 0; k0 < D; k0 += 16) {
        float4 a0 = *reinterpret_cast<const float4*>(
            &g_ctx[(size_t)(row0 + ar) * D + k0 + akc]);
        float4 a1 = *reinterpret_cast<const float4*>(
            &g_ctx[(size_t)(row0 + ar + 64) * D + k0 + akc]);
        float4 w0 = *reinterpret_cast<const float4*>(
            &W3[(size_t)(col0 + bnr) * D + k0 + bkc]);
        float4 w1 = *reinterpret_cast<const float4*>(
            &W3[(size_t)(col0 + bnr) * D + k0 + bkc + 4]);
        __syncthreads();
        {
            const float va0[4] = {a0.x, a0.y, a0.z, a0.w};
            const float va1[4] = {a1.x, a1.y, a1.z, a1.w};
#pragma unroll
            for (int j = 0; j < 4; ++j) {
                uint32_t h, l;
                tf32_split(va0[j], h, l); Ah[akc + j][ar] = h;      Al[akc + j][ar] = l;
                tf32_split(va1[j], h, l); Ah[akc + j][ar + 64] = h; Al[akc + j][ar + 64] = l;
            }
            const float w[8] = {w0.x, w0.y, w0.z, w0.w, w1.x, w1.y, w1.z, w1.w};
#pragma unroll
            for (int j = 0; j < 8; ++j) {
                uint32_t h, l;
                tf32_split(w[j], h, l); Bh[bkc + j][bnr] = h; Bl[bkc + j][bnr] = l;
            }
        }
        __syncthreads();
#pragma unroll
        for (int ks = 0; ks < 2; ++ks) {
            const int k8 = ks * 8;
            const int fr = lane >> 2, fc = lane & 3;
            uint32_t ah[4][4], al[4][4], bh[4][2], bl[4][2];
#pragma unroll
            for (int mt = 0; mt < 4; ++mt) {
                const int mb = wy * 64 + mt * 16;
                ah[mt][0] = Ah[k8 + fc][mb + fr];     al[mt][0] = Al[k8 + fc][mb + fr];
                ah[mt][1] = Ah[k8 + fc][mb + fr + 8]; al[mt][1] = Al[k8 + fc][mb + fr + 8];
                ah[mt][2] = Ah[k8 + fc + 4][mb + fr];     al[mt][2] = Al[k8 + fc + 4][mb + fr];
                ah[mt][3] = Ah[k8 + fc + 4][mb + fr + 8]; al[mt][3] = Al[k8 + fc + 4][mb + fr + 8];
            }
#pragma unroll
            for (int nt = 0; nt < 4; ++nt) {
                const int nb = wx * 32 + nt * 8;
                bh[nt][0] = Bh[k8 + fc][nb + fr];     bl[nt][0] = Bl[k8 + fc][nb + fr];
                bh[nt][1] = Bh[k8 + fc + 4][nb + fr]; bl[nt][1] = Bl[k8 + fc + 4][nb + fr];
            }
#pragma unroll
            for (int mt = 0; mt < 4; ++mt)
#pragma unroll
                for (int nt = 0; nt < 4; ++nt) {
                    mma_tf32(acc[mt][nt], ah[mt], bl[nt]);
                    mma_tf32(acc[mt][nt], al[mt], bh[nt]);
                    mma_tf32(acc[mt][nt], ah[mt], bh[nt]);
                }
        }
    }
    const int fr = lane >> 2, fc = lane & 3;
#pragma unroll
    for (int mt = 0; mt < 4; ++mt)
#pragma unroll
        for (int nt = 0; nt < 4; ++nt) {
            const int col = col0 + wx * 32 + nt * 8 + 2 * fc;
            const float bx = b3[col], by = b3[col + 1];
#pragma unroll
            for (int h = 0; h < 2; ++h) {
                const int r = row0 + wy * 64 + mt * 16 + fr + 8 * h;
                const int b = r >> 10, l = r & (L_IN - 1);
                float2 v = {acc[mt][nt][2 * h] + bx, acc[mt][nt][2 * h + 1] + by};
                *reinterpret_cast<float2*>(&out[((size_t)l * BATCH + b) * D + col]) = v;
            }
        }
}

// ---------------------------------------------------------------------------
extern "C" void kernel_launch(void* const* d_in, const int* in_sizes, int n_in,
                              void* d_out, int out_size)
{
    const float* in_seq   = (const float*)d_in[0];
    const float* enc_seq  = (const float*)d_in[1];
    const float* prev_tgt = (const float*)d_in[2];
    const float* W_in2enc = (const float*)d_in[3];
    const float* b_in2enc = (const float*)d_in[4];
    const float* W_lab2enc= (const float*)d_in[5];
    const float* b_lab2enc= (const float*)d_in[6];
    const float* W_enc2in = (const float*)d_in[7];
    const float* b_enc2in = (const float*)d_in[8];
    float* out = (float*)d_out;

    k_proj1  <<<dim3(D / TN, ROWS / TM), 256>>>(in_seq,   W_in2enc,  b_in2enc);
    k_proj2  <<<dim3(D / TN, ROWS / TM), 256>>>(prev_tgt, W_lab2enc, b_lab2enc);
    k_scores <<<dim3(L_ENC / TN, L_IN / TM, BATCH), 256>>>(enc_seq);
    k_rowsum <<<BATCH * L_IN / 8, 512>>>();
    k_ctx_tc <<<dim3(D / 128, L_IN / 128, BATCH), 256>>>(enc_seq);
    k_out_tc <<<dim3(D / 128, ROWS / 128), 256>>>(W_enc2in, b_enc2in, out);
}